// round 8
// baseline (speedup 1.0000x reference)
#include <cuda_runtime.h>
#include <cuda_bf16.h>
#include <math.h>
#include <stdint.h>

#define SQL 48
#define BB  128
#define HDIM 100
#define LDXP 1120   // padded feature width (bf16 rows, 16B-aligned)

typedef unsigned long long ull;

// ------------------------- scratch (device globals; no allocs) -------------
__device__ __nv_bfloat16 g_PX[SQL*BB*LDXP];    // query features (bf16)
__device__ __nv_bfloat16 g_HX[SQL*BB*LDXP];    // support features
__device__ __nv_bfloat16 g_W16[5*400*LDXP];    // all layers' wih in bf16 (zero-padded)
__device__ float g_GP[SQL*BB*400];             // x@wih^T + biases (query)
__device__ float g_GH[SQL*BB*400];             // (support)
__device__ float g_PH[SQL*BB*HDIM];            // hidden states (query, fp32)
__device__ float g_HHs[SQL*BB*HDIM];           // (support)

__constant__ int c_dims[5] = {316, 516, 716, 916, 1116};

// ------------------------- f32x2 helpers -----------------------------------
__device__ __forceinline__ void fma2(ull &d, ull a, ull b) {
    asm("fma.rn.f32x2 %0, %1, %2, %0;" : "+l"(d) : "l"(a), "l"(b));
}
__device__ __forceinline__ ull bcast2(float x) {
    ull r; asm("mov.b64 %0, {%1, %1};" : "=l"(r) : "f"(x)); return r;
}
__device__ __forceinline__ ull pack2(float x, float y) {
    ull r; asm("mov.b64 %0, {%1, %2};" : "=l"(r) : "f"(x), "f"(y)); return r;
}
__device__ __forceinline__ float hsum2(ull a) {
    float2 v = *reinterpret_cast<float2*>(&a); return v.x + v.y;
}

// ------------------- fused prep: wih->bf16 convert + embedding -------------
// blocks [0, 2000): convert one wih row; blocks [2000, 14288): embed one token
__global__ __launch_bounds__(128) void prep_kernel(
    const float* __restrict__ W0, const float* __restrict__ W1,
    const float* __restrict__ W2, const float* __restrict__ W3,
    const float* __restrict__ W4,
    const int* __restrict__ q_words, const int* __restrict__ q_chars,
    const int* __restrict__ s_words, const int* __restrict__ s_chars,
    const float* __restrict__ word_emb, const float* __restrict__ char_emb,
    const float* __restrict__ conv_w, const float* __restrict__ conv_b)
{
    int blk = blockIdx.x;
    int tid = threadIdx.x;

    if (blk < 2000) {   // ---- weight conversion path ----
        int layer = blk / 400;
        int row   = blk % 400;
        const float* Wp[5] = {W0, W1, W2, W3, W4};
        const float* W = Wp[layer];
        int d = c_dims[layer];
        __nv_bfloat16* dst = g_W16 + ((size_t)layer*400 + row)*LDXP;
        for (int c = tid; c < LDXP; c += 128) {
            float v = (c < d) ? W[(size_t)row*d + c] : 0.f;
            dst[c] = __float2bfloat16(v);
        }
        return;
    }

    // ---- embedding path ----
    int e = blk - 2000;             // 0..12287
    int which = e / 6144;
    int m = e % 6144;
    const int* words = which ? s_words : q_words;
    const int* chars = which ? s_chars : q_chars;
    __nv_bfloat16* X = which ? g_HX : g_PX;
    int b = m / SQL;
    int s = m % SQL;

    __shared__ float ce[256];
    __shared__ float wsh[48];
    __shared__ float cb[16];
    if (tid < 48) wsh[tid] = conv_w[tid];
    if (tid < 16) cb[tid]  = conv_b[tid];

    for (int idx = tid; idx < 256; idx += 128) {
        int c = idx >> 4, dd = idx & 15;
        int ch = chars[(b*SQL + s)*16 + c];
        ce[idx] = char_emb[ch*16 + dd];
    }
    int w = words[b*SQL + s];
    int row = s*BB + b;
    if (tid < 75) {   // 300 floats = 75 float4
        float4 v = *reinterpret_cast<const float4*>(&word_emb[(size_t)w*300 + tid*4]);
        __nv_bfloat162 lo = __float22bfloat162_rn(make_float2(v.x, v.y));
        __nv_bfloat162 hi = __float22bfloat162_rn(make_float2(v.z, v.w));
        *reinterpret_cast<__nv_bfloat162*>(&X[(size_t)row*LDXP + tid*4])     = lo;
        *reinterpret_cast<__nv_bfloat162*>(&X[(size_t)row*LDXP + tid*4 + 2]) = hi;
    }
    __syncthreads();

    int o = tid >> 3, l = tid & 7;
    float w0 = wsh[o*3], w1 = wsh[o*3+1], w2 = wsh[o*3+2];
    float mx = -1e30f;
    for (int t = l; t < 254; t += 8) {
        float v = ce[t]*w0 + ce[t+1]*w1 + ce[t+2]*w2;
        mx = fmaxf(mx, v);
    }
    #pragma unroll
    for (int off = 4; off; off >>= 1)
        mx = fmaxf(mx, __shfl_down_sync(0xffffffffu, mx, off, 8));
    if (l == 0) {
        float v = mx + cb[o];
        if (b != 0) v = fmaxf(v, 0.f);   // reference quirk: batch row 0 skips relu
        X[(size_t)row*LDXP + 300 + o] = __float2bfloat16(v);
    }
}

// ------------------------- bf16 tensor-core GEMM (cp.async) ----------------
#define SAW 72
#define SA_ELEMS (128*SAW)
#define SB_ELEMS (64*SAW)

__device__ __forceinline__ void mma_bf16(float* c, const uint32_t* a, const uint32_t* b) {
    asm volatile(
        "mma.sync.aligned.m16n8k16.row.col.f32.bf16.bf16.f32 "
        "{%0,%1,%2,%3}, {%4,%5,%6,%7}, {%8,%9}, {%0,%1,%2,%3};"
        : "+f"(c[0]), "+f"(c[1]), "+f"(c[2]), "+f"(c[3])
        : "r"(a[0]), "r"(a[1]), "r"(a[2]), "r"(a[3]), "r"(b[0]), "r"(b[1]));
}
__device__ __forceinline__ void ldsm_x4(uint32_t& r0, uint32_t& r1, uint32_t& r2, uint32_t& r3,
                                        uint32_t addr) {
    asm volatile("ldmatrix.sync.aligned.m8n8.x4.shared.b16 {%0,%1,%2,%3}, [%4];"
        : "=r"(r0), "=r"(r1), "=r"(r2), "=r"(r3) : "r"(addr));
}
__device__ __forceinline__ void cp_async16(uint32_t smem, const void* g, int src_bytes) {
    asm volatile("cp.async.cg.shared.global [%0], [%1], 16, %2;"
        :: "r"(smem), "l"(g), "r"(src_bytes));
}
__device__ __forceinline__ void cp_commit() {
    asm volatile("cp.async.commit_group;");
}
template<int N>
__device__ __forceinline__ void cp_wait() {
    asm volatile("cp.async.wait_group %0;" :: "n"(N));
}

__global__ __launch_bounds__(256) void gemm_wih_bf16(
    const float* __restrict__ bih, const float* __restrict__ bhh, int d, int layer)
{
    const __nv_bfloat16* X = blockIdx.z ? g_HX : g_PX;
    const __nv_bfloat16* Wb = g_W16 + (size_t)layer*400*LDXP;
    float* Y               = blockIdx.z ? g_GH : g_GP;
    extern __shared__ __align__(16) unsigned char smraw[];
    __nv_bfloat16* SA = (__nv_bfloat16*)smraw;        // [2][128*72]
    __nv_bfloat16* SB = SA + 2*SA_ELEMS;              // [2][64*72]
    uint32_t sa_base = (uint32_t)__cvta_generic_to_shared(SA);
    uint32_t sb_base = (uint32_t)__cvta_generic_to_shared(SB);

    int tid  = threadIdx.x;
    int wid  = tid >> 5, lane = tid & 31;
    int wm   = wid >> 1, wn = wid & 1;
    int m0   = blockIdx.y * 128;
    int n0   = blockIdx.x * 64;
    int lg   = lane >> 2;
    int lk   = lane & 3;

    int a_roff = (wm*32 + (lane & 15)) * SAW + ((lane & 16) ? 8 : 0);
    int b_roff = (wn*32 + (lane & 7) + ((lane & 16) ? 8 : 0)) * SAW + ((lane & 8) ? 8 : 0);

    int arow = tid >> 3, ac16 = tid & 7;
    int brow = tid >> 3;

    float acc[2][4][4];
    #pragma unroll
    for (int i = 0; i < 2; i++)
        #pragma unroll
        for (int j = 0; j < 4; j++)
            #pragma unroll
            for (int r = 0; r < 4; r++) acc[i][j][r] = 0.f;

    int nChunk = (d + 63) >> 6;

    auto issueStage = [&](int st, int k0) {
        uint32_t sa = sa_base + st*SA_ELEMS*2;
        uint32_t sb = sb_base + st*SB_ELEMS*2;
        #pragma unroll
        for (int q = 0; q < 4; q++) {
            int row = arow + q*32;
            int c0  = k0 + ac16*8;
            int nb  = (d - c0)*2;
            nb = nb < 0 ? 0 : (nb > 16 ? 16 : nb);
            int cs  = nb ? c0 : 0;
            cp_async16(sa + (row*SAW + ac16*8)*2,
                       &X[(size_t)(m0+row)*LDXP + cs], nb);
        }
        #pragma unroll
        for (int q = 0; q < 2; q++) {
            int row = brow + q*32;
            int nr  = n0 + row;
            int nb  = (nr < 400) ? 16 : 0;
            int rc  = (nr < 400) ? nr : 0;
            int c0  = k0 + ac16*8;
            cp_async16(sb + (row*SAW + ac16*8)*2,
                       &Wb[(size_t)rc*LDXP + c0], nb);
        }
        cp_commit();
    };

    issueStage(0, 0);

    for (int kc = 0; kc < nChunk; kc++) {
        int cur = kc & 1;
        bool more = (kc + 1 < nChunk);
        if (more) issueStage(cur ^ 1, (kc+1) << 6);
        if (more) cp_wait<1>(); else cp_wait<0>();
        __syncthreads();

        uint32_t sa_u = sa_base + cur*SA_ELEMS*2;
        uint32_t sb_u = sb_base + cur*SB_ELEMS*2;
        #pragma unroll
        for (int s = 0; s < 4; s++) {
            uint32_t a[2][4], b[4][2];
            #pragma unroll
            for (int mt = 0; mt < 2; mt++)
                ldsm_x4(a[mt][0], a[mt][1], a[mt][2], a[mt][3],
                        sa_u + 2*(a_roff + mt*16*SAW + s*16));
            #pragma unroll
            for (int ntp = 0; ntp < 2; ntp++) {
                uint32_t r0, r1, r2, r3;
                ldsm_x4(r0, r1, r2, r3, sb_u + 2*(b_roff + ntp*16*SAW + s*16));
                b[2*ntp][0] = r0; b[2*ntp][1] = r1;
                b[2*ntp+1][0] = r2; b[2*ntp+1][1] = r3;
            }
            #pragma unroll
            for (int mt = 0; mt < 2; mt++)
                #pragma unroll
                for (int nt = 0; nt < 4; nt++)
                    mma_bf16(acc[mt][nt], a[mt], b[nt]);
        }
        __syncthreads();
    }

    #pragma unroll
    for (int mt = 0; mt < 2; mt++) {
        int row0 = m0 + wm*32 + mt*16 + lg;
        #pragma unroll
        for (int nt = 0; nt < 4; nt++) {
            int col0 = n0 + wn*32 + nt*8 + 2*lk;
            if (col0 < 400) {
                float bs0 = bih[col0]   + bhh[col0];
                float bs1 = bih[col0+1] + bhh[col0+1];
                Y[(size_t)row0*400 + col0]       = acc[mt][nt][0] + bs0;
                Y[(size_t)row0*400 + col0+1]     = acc[mt][nt][1] + bs1;
                Y[(size_t)(row0+8)*400 + col0]   = acc[mt][nt][2] + bs0;
                Y[(size_t)(row0+8)*400 + col0+1] = acc[mt][nt][3] + bs1;
            }
        }
    }
}

// ------------------------- LSTM recurrence ---------------------------------
// Gate-per-thread: tid = j*4 + g (400 active of 512). Each thread owns one
// whh gate row (w2[50] f32x2 = 100 regs), reads h via broadcast LDS.128,
// computes its gate fully; 3 quad-shuffles deliver all 4 gates to leader g=0.
// h double-buffered by step parity -> ONE __syncthreads per step.
__device__ __forceinline__ float sigmf(float x) { return 1.f/(1.f+__expf(-x)); }
__device__ __forceinline__ float tanhf_fast(float x) { return 1.f - 2.f/(__expf(2.f*x)+1.f); }

__global__ __launch_bounds__(512,1) void lstm_kernel(
    const float* __restrict__ whh, int dk, int writeX)
{
    int blk = blockIdx.x;        // 0..127
    int seq = blk >> 6;
    int bp  = blk & 63;
    const float* G = seq ? g_GH : g_GP;
    float* Hout         = seq ? g_HHs : g_PH;
    __nv_bfloat16* Xout = seq ? g_HX  : g_PX;
    int bA = bp, bB = bp + 64;

    int tid  = threadIdx.x;
    bool act = tid < 400;
    int j    = tid >> 2;         // 0..99 (for act threads)
    int g    = tid & 3;          // gate: 0=i, 1=f, 2=g, 3=o
    int lane = tid & 31;
    unsigned qmask = 0xFu << (lane & ~3);   // this thread's quad

    __shared__ __align__(16) float h_s[2][2][104];   // [parity][bi][j]

    ull w2[50];
    if (act) {
        const float* wr = whh + (size_t)(g*100 + j)*100;
        #pragma unroll
        for (int m = 0; m < 50; m++)
            w2[m] = *reinterpret_cast<const ull*>(wr + 2*m);
    }

    int goff = g*100 + j;
    float grA = 0.f, grB = 0.f;
    if (act) {
        grA = G[(size_t)bA*400 + goff];
        grB = G[(size_t)bB*400 + goff];
    }
    float cA = 0.f, cB = 0.f;
    if (tid < 104) { h_s[0][0][tid] = 0.f; h_s[0][1][tid] = 0.f; }
    __syncthreads();

    for (int t = 0; t < 48; t++) {
        int p = t & 1, np = p ^ 1;
        float totA = 0.f, totB = 0.f;
        if (act) {
            const float4* hA = reinterpret_cast<const float4*>(h_s[p][0]);
            const float4* hB = reinterpret_cast<const float4*>(h_s[p][1]);
            ull aA = 0, aB = 0;
            #pragma unroll
            for (int m = 0; m < 25; m++) {
                float4 va = hA[m];
                float4 vb = hB[m];
                fma2(aA, pack2(va.x, va.y), w2[2*m]);
                fma2(aA, pack2(va.z, va.w), w2[2*m+1]);
                fma2(aB, pack2(vb.x, vb.y), w2[2*m]);
                fma2(aB, pack2(vb.z, vb.w), w2[2*m+1]);
            }
            totA = hsum2(aA) + grA;
            totB = hsum2(aB) + grB;
            if (t + 1 < 48) {   // prefetch next step's gate value
                grA = G[(size_t)((t+1)*128 + bA)*400 + goff];
                grB = G[(size_t)((t+1)*128 + bB)*400 + goff];
            }
            // quad gather: leader (g==0) receives all four gate sums
            float a1 = __shfl_down_sync(qmask, totA, 1, 4);
            float a2 = __shfl_down_sync(qmask, totA, 2, 4);
            float a3 = __shfl_down_sync(qmask, totA, 3, 4);
            float b1 = __shfl_down_sync(qmask, totB, 1, 4);
            float b2 = __shfl_down_sync(qmask, totB, 2, 4);
            float b3 = __shfl_down_sync(qmask, totB, 3, 4);
            if (g == 0) {
                cA = sigmf(a1)*cA + sigmf(totA)*tanhf_fast(a2);
                float hA2 = sigmf(a3)*tanhf_fast(cA);
                cB = sigmf(b1)*cB + sigmf(totB)*tanhf_fast(b2);
                float hB2 = sigmf(b3)*tanhf_fast(cB);
                h_s[np][0][j] = hA2;
                h_s[np][1][j] = hB2;
                Hout[(size_t)(t*128+bA)*100 + j] = hA2;
                Hout[(size_t)(t*128+bB)*100 + j] = hB2;
                if (writeX) {
                    Xout[(size_t)(t*128+bA)*LDXP + dk + 100 + j] = __float2bfloat16(hA2);
                    Xout[(size_t)(t*128+bB)*LDXP + dk + 100 + j] = __float2bfloat16(hB2);
                }
            }
        }
        __syncthreads();
    }
}

// ------------------------- cross attention ---------------------------------
__global__ __launch_bounds__(256) void attn_kernel(int dk)
{
    extern __shared__ __align__(16) float smem[];
    float* hp   = smem;            // 4800
    float* hh   = smem + 4800;     // 4800
    float* attn = smem + 9600;     // 2304
    float* E    = smem + 11904;    // 2304
    float* rmax = smem + 14208;    // 48
    float* rsum = rmax + 48;
    float* cmax = rsum + 48;
    float* csum = cmax + 48;

    int b = blockIdx.x;
    int tid = threadIdx.x;

    for (int idx = tid; idx < 2400; idx += 256) {
        int s = idx / 50, h2 = (idx % 50)*2;
        *reinterpret_cast<float2*>(&hp[s*100+h2]) =
            *reinterpret_cast<const float2*>(&g_PH [(size_t)(s*128+b)*100 + h2]);
        *reinterpret_cast<float2*>(&hh[s*100+h2]) =
            *reinterpret_cast<const float2*>(&g_HHs[(size_t)(s*128+b)*100 + h2]);
    }
    __syncthreads();

    for (int idx = tid; idx < 2304; idx += 256) {
        int p = idx / 48, q = idx % 48;
        const ull* ap = reinterpret_cast<const ull*>(hp + p*100);
        const ull* bq = reinterpret_cast<const ull*>(hh + q*100);
        ull acc = 0;
        #pragma unroll 5
        for (int i = 0; i < 50; i++) fma2(acc, ap[i], bq[i]);
        attn[idx] = hsum2(acc);
    }
    __syncthreads();

    if (tid < 48) {
        float m = -1e30f;
        for (int q = 0; q < 48; q++) m = fmaxf(m, attn[tid*48+q]);
        float s2 = 0.f;
        for (int q = 0; q < 48; q++) s2 += expf(attn[tid*48+q]-m);
        rmax[tid] = m; rsum[tid] = s2;
    } else if (tid >= 128 && tid < 176) {
        int q = tid - 128;
        float m = -1e30f;
        for (int p = 0; p < 48; p++) m = fmaxf(m, attn[p*48+q]);
        float s2 = 0.f;
        for (int p = 0; p < 48; p++) s2 += expf(attn[p*48+q]-m);
        cmax[q] = m; csum[q] = s2;
    }
    __syncthreads();

    for (int idx = tid; idx < 2304; idx += 256) {
        int p = idx / 48;
        E[idx] = expf(attn[idx]-rmax[p]) / rsum[p];
    }
    __syncthreads();
    for (int idx = tid; idx < 2400; idx += 256) {   // a_p
        int p = idx / 50, h2p = idx % 50;
        const ull* hh2 = reinterpret_cast<const ull*>(hh) + h2p;
        ull acc = 0;
        #pragma unroll 4
        for (int q = 0; q < 48; q++) fma2(acc, bcast2(E[p*48+q]), hh2[q*50]);
        float2 r = *reinterpret_cast<float2*>(&acc);
        *reinterpret_cast<__nv_bfloat162*>(&g_PX[(size_t)(p*128+b)*LDXP + dk + 2*h2p]) =
            __float22bfloat162_rn(r);
    }
    __syncthreads();

    for (int idx = tid; idx < 2304; idx += 256) {
        int q = idx % 48;
        E[idx] = expf(attn[idx]-cmax[q]) / csum[q];
    }
    __syncthreads();
    for (int idx = tid; idx < 2400; idx += 256) {   // a_h
        int q = idx / 50, h2p = idx % 50;
        const ull* hp2 = reinterpret_cast<const ull*>(hp) + h2p;
        ull acc = 0;
        #pragma unroll 4
        for (int p = 0; p < 48; p++) fma2(acc, bcast2(E[p*48+q]), hp2[p*50]);
        float2 r = *reinterpret_cast<float2*>(&acc);
        *reinterpret_cast<__nv_bfloat162*>(&g_HX[(size_t)(q*128+b)*LDXP + dk + 2*h2p]) =
            __float22bfloat162_rn(r);
    }
}

// ------------------------- pooling + FC head -------------------------------
__global__ __launch_bounds__(256) void head_kernel(
    const float* __restrict__ fcl_w, const float* __restrict__ fcl_b,
    const float* __restrict__ last_w, const float* __restrict__ last_b,
    float* __restrict__ out)
{
    __shared__ __align__(16) float feats[500];
    __shared__ float o1[800];
    __shared__ float red[256];
    int b = blockIdx.x, tid = threadIdx.x;

    if (tid < 100) {
        float hq = -1e30f, hs = -1e30f;
        for (int s = 0; s < 48; s++) {
            hq = fmaxf(hq, g_PH [(size_t)(s*128+b)*100 + tid]);
            hs = fmaxf(hs, g_HHs[(size_t)(s*128+b)*100 + tid]);
        }
        feats[tid]       = hq;
        feats[100 + tid] = hs;
        feats[200 + tid] = hs - hq;
        feats[300 + tid] = hq * hs;
        feats[400 + tid] = fabsf(hq - hs);
    }
    __syncthreads();

    for (int o = tid; o < 800; o += 256) {
        const ull* f2 = reinterpret_cast<const ull*>(feats);
        const ull* w2 = reinterpret_cast<const ull*>(fcl_w + (size_t)o*500);
        ull acc = 0;
        #pragma unroll 5
        for (int k = 0; k < 250; k++) fma2(acc, f2[k], w2[k]);
        o1[o] = fmaxf(hsum2(acc) + fcl_b[o], 0.f);
    }
    __syncthreads();

    for (int cc = 0; cc < 2; cc++) {
        float pa = 0.f;
        for (int o = tid; o < 800; o += 256) pa += o1[o]*last_w[cc*800+o];
        red[tid] = pa;
        __syncthreads();
        for (int off = 128; off; off >>= 1) {
            if (tid < off) red[tid] += red[tid+off];
            __syncthreads();
        }
        if (tid == 0) {
            float v = red[0] + last_b[cc];
            out[b*2+cc] = 1.f/(1.f+expf(-v));
        }
        __syncthreads();
    }
}

// ------------------------- launch ------------------------------------------
extern "C" void kernel_launch(void* const* d_in, const int* in_sizes, int n_in,
                              void* d_out, int out_size)
{
    const int*   q_words  = (const int*)d_in[0];
    const int*   q_chars  = (const int*)d_in[1];
    const int*   s_words  = (const int*)d_in[2];
    const int*   s_chars  = (const int*)d_in[3];
    const float* word_emb = (const float*)d_in[4];
    const float* char_emb = (const float*)d_in[5];
    const float* conv_w   = (const float*)d_in[6];
    const float* conv_b   = (const float*)d_in[7];
    const float* fcl_w    = (const float*)d_in[28];
    const float* fcl_b    = (const float*)d_in[29];
    const float* last_w   = (const float*)d_in[30];
    const float* last_b   = (const float*)d_in[31];
    float* out = (float*)d_out;

    const int gemm_smem = 2*(SA_ELEMS + SB_ELEMS)*2;   // 55296 bytes
    cudaFuncSetAttribute(gemm_wih_bf16, cudaFuncAttributeMaxDynamicSharedMemorySize, gemm_smem);
    cudaFuncSetAttribute(attn_kernel, cudaFuncAttributeMaxDynamicSharedMemorySize, 57600);

    // fused: weight conversion (all layers) + embedding, one launch
    prep_kernel<<<14288,128>>>(
        (const float*)d_in[8],  (const float*)d_in[12], (const float*)d_in[16],
        (const float*)d_in[20], (const float*)d_in[24],
        q_words, q_chars, s_words, s_chars,
        word_emb, char_emb, conv_w, conv_b);

    const int dims[5] = {316, 516, 716, 916, 1116};
    for (int k = 0; k < 5; k++) {
        const float* whh = (const float*)d_in[9+4*k];
        const float* bih = (const float*)d_in[10+4*k];
        const float* bhh = (const float*)d_in[11+4*k];
        dim3 gg(7, 48, 2);
        gemm_wih_bf16<<<gg, 256, gemm_smem>>>(bih, bhh, dims[k], k);
        lstm_kernel<<<128, 512>>>(whh, dims[k], (k < 4) ? 1 : 0);
        if (k < 4) attn_kernel<<<128, 256, 57600>>>(dims[k]);
    }
    head_kernel<<<128, 256>>>(fcl_w, fcl_b, last_w, last_b, out);
}

// round 9
// speedup vs baseline: 1.2285x; 1.2285x over previous
#include <cuda_runtime.h>
#include <cuda_bf16.h>
#include <math.h>
#include <stdint.h>

#define SQL 48
#define BB  128
#define HDIM 100
#define LDXP 1120   // padded feature width (bf16 rows, 16B-aligned)

typedef unsigned long long ull;

// ------------------------- scratch (device globals; no allocs) -------------
__device__ __nv_bfloat16 g_PX[SQL*BB*LDXP];    // query features (bf16)
__device__ __nv_bfloat16 g_HX[SQL*BB*LDXP];    // support features
__device__ __nv_bfloat16 g_W16[5*400*LDXP];    // all layers' wih in bf16 (zero-padded)
__device__ float g_GP[SQL*BB*400];             // x@wih^T + biases (query)
__device__ float g_GH[SQL*BB*400];             // (support)
__device__ float g_PH[SQL*BB*HDIM];            // hidden states (query, fp32)
__device__ float g_HHs[SQL*BB*HDIM];           // (support)

__constant__ int c_dims[5] = {316, 516, 716, 916, 1116};

// ------------------------- f32x2 helpers -----------------------------------
__device__ __forceinline__ void fma2(ull &d, ull a, ull b) {
    asm("fma.rn.f32x2 %0, %1, %2, %0;" : "+l"(d) : "l"(a), "l"(b));
}
__device__ __forceinline__ ull bcast2(float x) {
    ull r; asm("mov.b64 %0, {%1, %1};" : "=l"(r) : "f"(x)); return r;
}
__device__ __forceinline__ float hsum2(ull a) {
    float2 v = *reinterpret_cast<float2*>(&a); return v.x + v.y;
}

// ------------------- fused prep: wih->bf16 convert + embedding -------------
__global__ __launch_bounds__(128) void prep_kernel(
    const float* __restrict__ W0, const float* __restrict__ W1,
    const float* __restrict__ W2, const float* __restrict__ W3,
    const float* __restrict__ W4,
    const int* __restrict__ q_words, const int* __restrict__ q_chars,
    const int* __restrict__ s_words, const int* __restrict__ s_chars,
    const float* __restrict__ word_emb, const float* __restrict__ char_emb,
    const float* __restrict__ conv_w, const float* __restrict__ conv_b)
{
    int blk = blockIdx.x;
    int tid = threadIdx.x;

    if (blk < 2000) {   // ---- weight conversion path ----
        int layer = blk / 400;
        int row   = blk % 400;
        const float* Wp[5] = {W0, W1, W2, W3, W4};
        const float* W = Wp[layer];
        int d = c_dims[layer];
        __nv_bfloat16* dst = g_W16 + ((size_t)layer*400 + row)*LDXP;
        for (int c = tid; c < LDXP; c += 128) {
            float v = (c < d) ? W[(size_t)row*d + c] : 0.f;
            dst[c] = __float2bfloat16(v);
        }
        return;
    }

    // ---- embedding path ----
    int e = blk - 2000;             // 0..12287
    int which = e / 6144;
    int m = e % 6144;
    const int* words = which ? s_words : q_words;
    const int* chars = which ? s_chars : q_chars;
    __nv_bfloat16* X = which ? g_HX : g_PX;
    int b = m / SQL;
    int s = m % SQL;

    __shared__ float ce[256];
    __shared__ float wsh[48];
    __shared__ float cb[16];
    if (tid < 48) wsh[tid] = conv_w[tid];
    if (tid < 16) cb[tid]  = conv_b[tid];

    for (int idx = tid; idx < 256; idx += 128) {
        int c = idx >> 4, dd = idx & 15;
        int ch = chars[(b*SQL + s)*16 + c];
        ce[idx] = char_emb[ch*16 + dd];
    }
    int w = words[b*SQL + s];
    int row = s*BB + b;
    if (tid < 75) {   // 300 floats = 75 float4
        float4 v = *reinterpret_cast<const float4*>(&word_emb[(size_t)w*300 + tid*4]);
        __nv_bfloat162 lo = __float22bfloat162_rn(make_float2(v.x, v.y));
        __nv_bfloat162 hi = __float22bfloat162_rn(make_float2(v.z, v.w));
        *reinterpret_cast<__nv_bfloat162*>(&X[(size_t)row*LDXP + tid*4])     = lo;
        *reinterpret_cast<__nv_bfloat162*>(&X[(size_t)row*LDXP + tid*4 + 2]) = hi;
    }
    __syncthreads();

    int o = tid >> 3, l = tid & 7;
    float w0 = wsh[o*3], w1 = wsh[o*3+1], w2 = wsh[o*3+2];
    float mx = -1e30f;
    for (int t = l; t < 254; t += 8) {
        float v = ce[t]*w0 + ce[t+1]*w1 + ce[t+2]*w2;
        mx = fmaxf(mx, v);
    }
    #pragma unroll
    for (int off = 4; off; off >>= 1)
        mx = fmaxf(mx, __shfl_down_sync(0xffffffffu, mx, off, 8));
    if (l == 0) {
        float v = mx + cb[o];
        if (b != 0) v = fmaxf(v, 0.f);   // reference quirk: batch row 0 skips relu
        X[(size_t)row*LDXP + 300 + o] = __float2bfloat16(v);
    }
}

// ------------------------- bf16 tensor-core GEMM (cp.async) ----------------
#define SAW 72
#define SA_ELEMS (128*SAW)
#define SB_ELEMS (64*SAW)

__device__ __forceinline__ void mma_bf16(float* c, const uint32_t* a, const uint32_t* b) {
    asm volatile(
        "mma.sync.aligned.m16n8k16.row.col.f32.bf16.bf16.f32 "
        "{%0,%1,%2,%3}, {%4,%5,%6,%7}, {%8,%9}, {%0,%1,%2,%3};"
        : "+f"(c[0]), "+f"(c[1]), "+f"(c[2]), "+f"(c[3])
        : "r"(a[0]), "r"(a[1]), "r"(a[2]), "r"(a[3]), "r"(b[0]), "r"(b[1]));
}
__device__ __forceinline__ void ldsm_x4(uint32_t& r0, uint32_t& r1, uint32_t& r2, uint32_t& r3,
                                        uint32_t addr) {
    asm volatile("ldmatrix.sync.aligned.m8n8.x4.shared.b16 {%0,%1,%2,%3}, [%4];"
        : "=r"(r0), "=r"(r1), "=r"(r2), "=r"(r3) : "r"(addr));
}
__device__ __forceinline__ void cp_async16(uint32_t smem, const void* g, int src_bytes) {
    asm volatile("cp.async.cg.shared.global [%0], [%1], 16, %2;"
        :: "r"(smem), "l"(g), "r"(src_bytes));
}
__device__ __forceinline__ void cp_commit() {
    asm volatile("cp.async.commit_group;");
}
template<int N>
__device__ __forceinline__ void cp_wait() {
    asm volatile("cp.async.wait_group %0;" :: "n"(N));
}

__global__ __launch_bounds__(256) void gemm_wih_bf16(
    const float* __restrict__ bih, const float* __restrict__ bhh, int d, int layer)
{
    const __nv_bfloat16* X = blockIdx.z ? g_HX : g_PX;
    const __nv_bfloat16* Wb = g_W16 + (size_t)layer*400*LDXP;
    float* Y               = blockIdx.z ? g_GH : g_GP;
    extern __shared__ __align__(16) unsigned char smraw[];
    __nv_bfloat16* SA = (__nv_bfloat16*)smraw;        // [2][128*72]
    __nv_bfloat16* SB = SA + 2*SA_ELEMS;              // [2][64*72]
    uint32_t sa_base = (uint32_t)__cvta_generic_to_shared(SA);
    uint32_t sb_base = (uint32_t)__cvta_generic_to_shared(SB);

    int tid  = threadIdx.x;
    int wid  = tid >> 5, lane = tid & 31;
    int wm   = wid >> 1, wn = wid & 1;
    int m0   = blockIdx.y * 128;
    int n0   = blockIdx.x * 64;
    int lg   = lane >> 2;
    int lk   = lane & 3;

    int a_roff = (wm*32 + (lane & 15)) * SAW + ((lane & 16) ? 8 : 0);
    int b_roff = (wn*32 + (lane & 7) + ((lane & 16) ? 8 : 0)) * SAW + ((lane & 8) ? 8 : 0);

    int arow = tid >> 3, ac16 = tid & 7;
    int brow = tid >> 3;

    float acc[2][4][4];
    #pragma unroll
    for (int i = 0; i < 2; i++)
        #pragma unroll
        for (int j = 0; j < 4; j++)
            #pragma unroll
            for (int r = 0; r < 4; r++) acc[i][j][r] = 0.f;

    int nChunk = (d + 63) >> 6;

    auto issueStage = [&](int st, int k0) {
        uint32_t sa = sa_base + st*SA_ELEMS*2;
        uint32_t sb = sb_base + st*SB_ELEMS*2;
        #pragma unroll
        for (int q = 0; q < 4; q++) {
            int row = arow + q*32;
            int c0  = k0 + ac16*8;
            int nb  = (d - c0)*2;
            nb = nb < 0 ? 0 : (nb > 16 ? 16 : nb);
            int cs  = nb ? c0 : 0;
            cp_async16(sa + (row*SAW + ac16*8)*2,
                       &X[(size_t)(m0+row)*LDXP + cs], nb);
        }
        #pragma unroll
        for (int q = 0; q < 2; q++) {
            int row = brow + q*32;
            int nr  = n0 + row;
            int nb  = (nr < 400) ? 16 : 0;
            int rc  = (nr < 400) ? nr : 0;
            int c0  = k0 + ac16*8;
            cp_async16(sb + (row*SAW + ac16*8)*2,
                       &Wb[(size_t)rc*LDXP + c0], nb);
        }
        cp_commit();
    };

    issueStage(0, 0);

    for (int kc = 0; kc < nChunk; kc++) {
        int cur = kc & 1;
        bool more = (kc + 1 < nChunk);
        if (more) issueStage(cur ^ 1, (kc+1) << 6);
        if (more) cp_wait<1>(); else cp_wait<0>();
        __syncthreads();

        uint32_t sa_u = sa_base + cur*SA_ELEMS*2;
        uint32_t sb_u = sb_base + cur*SB_ELEMS*2;
        #pragma unroll
        for (int s = 0; s < 4; s++) {
            uint32_t a[2][4], b[4][2];
            #pragma unroll
            for (int mt = 0; mt < 2; mt++)
                ldsm_x4(a[mt][0], a[mt][1], a[mt][2], a[mt][3],
                        sa_u + 2*(a_roff + mt*16*SAW + s*16));
            #pragma unroll
            for (int ntp = 0; ntp < 2; ntp++) {
                uint32_t r0, r1, r2, r3;
                ldsm_x4(r0, r1, r2, r3, sb_u + 2*(b_roff + ntp*16*SAW + s*16));
                b[2*ntp][0] = r0; b[2*ntp][1] = r1;
                b[2*ntp+1][0] = r2; b[2*ntp+1][1] = r3;
            }
            #pragma unroll
            for (int mt = 0; mt < 2; mt++)
                #pragma unroll
                for (int nt = 0; nt < 4; nt++)
                    mma_bf16(acc[mt][nt], a[mt], b[nt]);
        }
        __syncthreads();
    }

    #pragma unroll
    for (int mt = 0; mt < 2; mt++) {
        int row0 = m0 + wm*32 + mt*16 + lg;
        #pragma unroll
        for (int nt = 0; nt < 4; nt++) {
            int col0 = n0 + wn*32 + nt*8 + 2*lk;
            if (col0 < 400) {
                float bs0 = bih[col0]   + bhh[col0];
                float bs1 = bih[col0+1] + bhh[col0+1];
                Y[(size_t)row0*400 + col0]       = acc[mt][nt][0] + bs0;
                Y[(size_t)row0*400 + col0+1]     = acc[mt][nt][1] + bs1;
                Y[(size_t)(row0+8)*400 + col0]   = acc[mt][nt][2] + bs0;
                Y[(size_t)(row0+8)*400 + col0+1] = acc[mt][nt][3] + bs1;
            }
        }
    }
}

// ------------------------- LSTM recurrence (proven R6 design) --------------
// 512 threads, 128 blocks; block handles (seq, bp) and (seq, bp+64).
// 5-way h split; whh packed as f32x2 pairs (fma.rn.f32x2 = 2 MAC/issue).
__device__ __forceinline__ float sigmf(float x) { return 1.f/(1.f+__expf(-x)); }
__device__ __forceinline__ float tanhf_fast(float x) { return 1.f - 2.f/(__expf(2.f*x)+1.f); }

__global__ __launch_bounds__(512,1) void lstm_kernel(
    const float* __restrict__ whh, int dk, int writeX)
{
    int blk = blockIdx.x;        // 0..127
    int seq = blk >> 6;
    int bp  = blk & 63;
    const float* G = seq ? g_GH : g_GP;
    float* Hout         = seq ? g_HHs : g_PH;
    __nv_bfloat16* Xout = seq ? g_HX  : g_PX;

    int tid  = threadIdx.x;
    int j    = tid % 100;
    int part = tid / 100;        // 0..4 producers; 5 idle tail

    __shared__ __align__(16) float  h_s[2][100];
    __shared__ __align__(16) float4 ps4[2][5][100];

    ull w2[4][10];
    if (part < 5) {
        #pragma unroll
        for (int q = 0; q < 4; q++)
            #pragma unroll
            for (int m = 0; m < 10; m++)
                w2[q][m] = *reinterpret_cast<const ull*>(
                    &whh[(size_t)(q*100 + j)*100 + part*20 + 2*m]);
    }

    int bi = part;               // combiner role for tid<200
    int b  = bi ? bp + 64 : bp;
    float c = 0.f;
    float gr0 = 0.f, gr1 = 0.f, gr2 = 0.f, gr3 = 0.f;
    if (tid < 200) {
        const float* G0 = G + (size_t)b*400;
        gr0 = G0[j]; gr1 = G0[100+j]; gr2 = G0[200+j]; gr3 = G0[300+j];
    }
    if (tid < 100) { h_s[0][tid] = 0.f; h_s[1][tid] = 0.f; }
    __syncthreads();

    for (int t = 0; t < 48; t++) {
        if (part < 5) {
            #pragma unroll
            for (int b2 = 0; b2 < 2; b2++) {
                const ull* hp = reinterpret_cast<const ull*>(&h_s[b2][part*20]);
                ull a0 = 0, a1 = 0, a2 = 0, a3 = 0;
                #pragma unroll
                for (int m = 0; m < 10; m++) {
                    ull h2 = hp[m];
                    fma2(a0, h2, w2[0][m]);
                    fma2(a1, h2, w2[1][m]);
                    fma2(a2, h2, w2[2][m]);
                    fma2(a3, h2, w2[3][m]);
                }
                ps4[b2][part][j] = make_float4(hsum2(a0), hsum2(a1), hsum2(a2), hsum2(a3));
            }
        }
        __syncthreads();
        if (tid < 200) {
            float gi = gr0, gf = gr1, gg = gr2, go = gr3;
            #pragma unroll
            for (int p = 0; p < 5; p++) {
                float4 v = ps4[bi][p][j];
                gi += v.x; gf += v.y; gg += v.z; go += v.w;
            }
            if (t + 1 < 48) {   // prefetch next step's gates
                const float* Gn = G + (size_t)((t+1)*128 + b)*400;
                gr0 = Gn[j]; gr1 = Gn[100+j]; gr2 = Gn[200+j]; gr3 = Gn[300+j];
            }
            c = sigmf(gf)*c + sigmf(gi)*tanhf_fast(gg);
            float h = sigmf(go)*tanhf_fast(c);
            h_s[bi][j] = h;
            Hout[(size_t)(t*128+b)*100 + j] = h;
            if (writeX)
                Xout[(size_t)(t*128+b)*LDXP + dk + 100 + j] = __float2bfloat16(h);
        }
        __syncthreads();
    }
}

// ------------------------- cross attention (split by side) -----------------
// grid (128, 2): side 0 computes a_p -> g_PX; side 1 computes a_h -> g_HX.
// Each block recomputes the 48x48 score matrix (cheap) but does only its own
// softmax + output GEMV. Quad-parallel softmax reductions.
__global__ __launch_bounds__(256) void attn_kernel(int dk)
{
    extern __shared__ __align__(16) float smem[];
    float* hp   = smem;            // 4800
    float* hh   = smem + 4800;     // 4800
    float* attn = smem + 9600;     // 2304 (overwritten by E in-place)
    float* smax = smem + 11904;    // 48
    float* sinv = smax + 48;       // 48

    int b    = blockIdx.x;
    int side = blockIdx.y;
    int tid  = threadIdx.x;

    for (int idx = tid; idx < 2400; idx += 256) {
        int s = idx / 50, h2 = (idx % 50)*2;
        *reinterpret_cast<float2*>(&hp[s*100+h2]) =
            *reinterpret_cast<const float2*>(&g_PH [(size_t)(s*128+b)*100 + h2]);
        *reinterpret_cast<float2*>(&hh[s*100+h2]) =
            *reinterpret_cast<const float2*>(&g_HHs[(size_t)(s*128+b)*100 + h2]);
    }
    __syncthreads();

    for (int idx = tid; idx < 2304; idx += 256) {
        int p = idx / 48, q = idx % 48;
        const ull* ap = reinterpret_cast<const ull*>(hp + p*100);
        const ull* bq = reinterpret_cast<const ull*>(hh + q*100);
        ull acc = 0;
        #pragma unroll 5
        for (int i = 0; i < 50; i++) fma2(acc, ap[i], bq[i]);
        attn[idx] = hsum2(acc);
    }
    __syncthreads();

    // softmax stats: 48 lines x 4 threads each (side 0: rows; side 1: cols)
    if (tid < 192) {
        int line = tid >> 2, sub = tid & 3;
        float m = -1e30f;
        if (side == 0) {
            for (int q = sub; q < 48; q += 4) m = fmaxf(m, attn[line*48+q]);
        } else {
            for (int p = sub; p < 48; p += 4) m = fmaxf(m, attn[p*48+line]);
        }
        m = fmaxf(m, __shfl_xor_sync(0xffffffffu, m, 1, 4));
        m = fmaxf(m, __shfl_xor_sync(0xffffffffu, m, 2, 4));
        float s2 = 0.f;
        if (side == 0) {
            for (int q = sub; q < 48; q += 4) s2 += expf(attn[line*48+q]-m);
        } else {
            for (int p = sub; p < 48; p += 4) s2 += expf(attn[p*48+line]-m);
        }
        s2 += __shfl_xor_sync(0xffffffffu, s2, 1, 4);
        s2 += __shfl_xor_sync(0xffffffffu, s2, 2, 4);
        if (sub == 0) { smax[line] = m; sinv[line] = 1.f/s2; }
    }
    __syncthreads();

    // E in place of attn
    for (int idx = tid; idx < 2304; idx += 256) {
        int line = side ? (idx % 48) : (idx / 48);
        attn[idx] = expf(attn[idx]-smax[line]) * sinv[line];
    }
    __syncthreads();

    if (side == 0) {   // a_p = E(rows) @ hh -> g_PX
        for (int idx = tid; idx < 2400; idx += 256) {
            int p = idx / 50, h2p = idx % 50;
            const ull* hh2 = reinterpret_cast<const ull*>(hh) + h2p;
            ull acc = 0;
            #pragma unroll 4
            for (int q = 0; q < 48; q++) fma2(acc, bcast2(attn[p*48+q]), hh2[q*50]);
            float2 r = *reinterpret_cast<float2*>(&acc);
            *reinterpret_cast<__nv_bfloat162*>(&g_PX[(size_t)(p*128+b)*LDXP + dk + 2*h2p]) =
                __float22bfloat162_rn(r);
        }
    } else {           // a_h = E(cols)^T @ hp -> g_HX
        for (int idx = tid; idx < 2400; idx += 256) {
            int q = idx / 50, h2p = idx % 50;
            const ull* hp2 = reinterpret_cast<const ull*>(hp) + h2p;
            ull acc = 0;
            #pragma unroll 4
            for (int p = 0; p < 48; p++) fma2(acc, bcast2(attn[p*48+q]), hp2[p*50]);
            float2 r = *reinterpret_cast<float2*>(&acc);
            *reinterpret_cast<__nv_bfloat162*>(&g_HX[(size_t)(q*128+b)*LDXP + dk + 2*h2p]) =
                __float22bfloat162_rn(r);
        }
    }
}

// ------------------------- pooling + FC head -------------------------------
__global__ __launch_bounds__(256) void head_kernel(
    const float* __restrict__ fcl_w, const float* __restrict__ fcl_b,
    const float* __restrict__ last_w, const float* __restrict__ last_b,
    float* __restrict__ out)
{
    __shared__ __align__(16) float feats[500];
    __shared__ float o1[800];
    __shared__ float red[256];
    int b = blockIdx.x, tid = threadIdx.x;

    if (tid < 100) {
        float hq = -1e30f, hs = -1e30f;
        for (int s = 0; s < 48; s++) {
            hq = fmaxf(hq, g_PH [(size_t)(s*128+b)*100 + tid]);
            hs = fmaxf(hs, g_HHs[(size_t)(s*128+b)*100 + tid]);
        }
        feats[tid]       = hq;
        feats[100 + tid] = hs;
        feats[200 + tid] = hs - hq;
        feats[300 + tid] = hq * hs;
        feats[400 + tid] = fabsf(hq - hs);
    }
    __syncthreads();

    for (int o = tid; o < 800; o += 256) {
        const ull* f2 = reinterpret_cast<const ull*>(feats);
        const ull* w2 = reinterpret_cast<const ull*>(fcl_w + (size_t)o*500);
        ull acc = 0;
        #pragma unroll 5
        for (int k = 0; k < 250; k++) fma2(acc, f2[k], w2[k]);
        o1[o] = fmaxf(hsum2(acc) + fcl_b[o], 0.f);
    }
    __syncthreads();

    for (int cc = 0; cc < 2; cc++) {
        float pa = 0.f;
        for (int o = tid; o < 800; o += 256) pa += o1[o]*last_w[cc*800+o];
        red[tid] = pa;
        __syncthreads();
        for (int off = 128; off; off >>= 1) {
            if (tid < off) red[tid] += red[tid+off];
            __syncthreads();
        }
        if (tid == 0) {
            float v = red[0] + last_b[cc];
            out[b*2+cc] = 1.f/(1.f+expf(-v));
        }
        __syncthreads();
    }
}

// ------------------------- launch ------------------------------------------
extern "C" void kernel_launch(void* const* d_in, const int* in_sizes, int n_in,
                              void* d_out, int out_size)
{
    const int*   q_words  = (const int*)d_in[0];
    const int*   q_chars  = (const int*)d_in[1];
    const int*   s_words  = (const int*)d_in[2];
    const int*   s_chars  = (const int*)d_in[3];
    const float* word_emb = (const float*)d_in[4];
    const float* char_emb = (const float*)d_in[5];
    const float* conv_w   = (const float*)d_in[6];
    const float* conv_b   = (const float*)d_in[7];
    const float* fcl_w    = (const float*)d_in[28];
    const float* fcl_b    = (const float*)d_in[29];
    const float* last_w   = (const float*)d_in[30];
    const float* last_b   = (const float*)d_in[31];
    float* out = (float*)d_out;

    const int gemm_smem = 2*(SA_ELEMS + SB_ELEMS)*2;   // 55296 bytes
    const int attn_smem = 12000*4;                     // 48000 bytes
    cudaFuncSetAttribute(gemm_wih_bf16, cudaFuncAttributeMaxDynamicSharedMemorySize, gemm_smem);
    cudaFuncSetAttribute(attn_kernel, cudaFuncAttributeMaxDynamicSharedMemorySize, attn_smem);

    // fused: weight conversion (all layers) + embedding, one launch
    prep_kernel<<<14288,128>>>(
        (const float*)d_in[8],  (const float*)d_in[12], (const float*)d_in[16],
        (const float*)d_in[20], (const float*)d_in[24],
        q_words, q_chars, s_words, s_chars,
        word_emb, char_emb, conv_w, conv_b);

    const int dims[5] = {316, 516, 716, 916, 1116};
    for (int k = 0; k < 5; k++) {
        const float* whh = (const float*)d_in[9+4*k];
        const float* bih = (const float*)d_in[10+4*k];
        const float* bhh = (const float*)d_in[11+4*k];
        dim3 gg(7, 48, 2);
        gemm_wih_bf16<<<gg, 256, gemm_smem>>>(bih, bhh, dims[k], k);
        lstm_kernel<<<128, 512>>>(whh, dims[k], (k < 4) ? 1 : 0);
        if (k < 4) {
            dim3 ga(128, 2);
            attn_kernel<<<ga, 256, attn_smem>>>(dims[k]);
        }
    }
    head_kernel<<<128, 256>>>(fcl_w, fcl_b, last_w, last_b, out);
}